// round 3
// baseline (speedup 1.0000x reference)
#include <cuda_runtime.h>
#include <math.h>

#define T_TOK 100352   // 32*56*56 tokens
#define DIM   128
#define INNER 512
#define QKV3  1536
#define MLPD  512
#define HEADS 4
#define DISP  3
#define NEGM  (-1e9f)

// ---------------- scratch (static device globals; no allocations) ----------------
__device__ float g_h  [T_TOK * DIM];    // running hidden state
__device__ float g_xn [T_TOK * DIM];    // LN output
__device__ float g_qkv[T_TOK * QKV3];   // qkv projections
__device__ float g_mid[T_TOK * INNER];  // attn-out merged / MLP hidden (both T x 512)

// ---------------- patch embed: x(32,3,224,224) -> h(T,128) ----------------
__global__ void patch_embed_kernel(const float* __restrict__ x,
                                   const float* __restrict__ w,
                                   const float* __restrict__ b,
                                   float* __restrict__ out)
{
    int t = blockIdx.x;            // token
    int n = threadIdx.x;           // out channel (128)
    __shared__ float s[48];
    int bb = t / 3136, rem = t % 3136, ph = rem / 56, pw = rem % 56;
    if (n < 48) {
        int c = n >> 4, pi = (n >> 2) & 3, pj = n & 3;
        s[n] = x[((size_t)(bb * 3 + c) * 224 + (ph * 4 + pi)) * 224 + (pw * 4 + pj)];
    }
    __syncthreads();
    float acc = b[n];
    #pragma unroll
    for (int f = 0; f < 48; f++) acc += s[f] * w[f * DIM + n];
    out[(size_t)t * DIM + n] = acc;
}

// ---------------- LayerNorm over 128 channels, one block per token ----------------
__global__ void ln_kernel(const float* __restrict__ x,
                          const float* __restrict__ g,
                          const float* __restrict__ b,
                          float* __restrict__ y)
{
    int t = blockIdx.x, c = threadIdx.x;
    float v = x[(size_t)t * DIM + c];
    __shared__ float red[4];
    float s = v;
    #pragma unroll
    for (int o = 16; o; o >>= 1) s += __shfl_xor_sync(~0u, s, o);
    if ((c & 31) == 0) red[c >> 5] = s;
    __syncthreads();
    float mean = (red[0] + red[1] + red[2] + red[3]) * (1.f / 128.f);
    __syncthreads();
    float d = v - mean;
    s = d * d;
    #pragma unroll
    for (int o = 16; o; o >>= 1) s += __shfl_xor_sync(~0u, s, o);
    if ((c & 31) == 0) red[c >> 5] = s;
    __syncthreads();
    float var = (red[0] + red[1] + red[2] + red[3]) * (1.f / 128.f);
    y[(size_t)t * DIM + c] = d * rsqrtf(var + 1e-5f) * g[c] + b[c];
}

// ---------------- SGEMM 128x128xK, 256 threads, 8x8 micro-tile ----------------
// Double-buffered smem + register prefetch; K compile-time for full unroll.
// OP: 0 = +bias(optional), 1 = +bias +residual R, 2 = +bias then exact GELU
__device__ __forceinline__ float gelu_f(float v)
{
    return 0.5f * v * (1.f + erff(v * 0.70710678118654752f));
}

template <int OP, int K, int N>
__global__ void __launch_bounds__(256)
sgemm_kernel(const float* __restrict__ A, const float* __restrict__ B,
             const float* __restrict__ bias, const float* __restrict__ R,
             float* __restrict__ C)
{
    __shared__ float As[2][8][128];
    __shared__ float Bs[2][8][128];
    int tid  = threadIdx.x;
    int row0 = blockIdx.y * 128, col0 = blockIdx.x * 128;
    int am = tid >> 1, ak = (tid & 1) * 4;   // A loader: row am, 4 consecutive k
    int bk = tid >> 5, bn = (tid & 31) * 4;  // B loader: row bk, 4 consecutive n
    int tx = tid & 15, ty = tid >> 4;

    float acc[8][8];
    #pragma unroll
    for (int r = 0; r < 8; r++)
        #pragma unroll
        for (int c = 0; c < 8; c++) acc[r][c] = 0.f;

    const float* Aptr = A + (size_t)(row0 + am) * K + ak;
    const float* Bptr = B + (size_t)bk * N + col0 + bn;

    // preload first K-step into buffer 0
    float4 a4 = *(const float4*)(Aptr);
    float4 b4 = *(const float4*)(Bptr);
    As[0][ak + 0][am] = a4.x; As[0][ak + 1][am] = a4.y;
    As[0][ak + 2][am] = a4.z; As[0][ak + 3][am] = a4.w;
    *(float4*)&Bs[0][bk][bn] = b4;
    __syncthreads();

    int buf = 0;
    #pragma unroll
    for (int k0 = 0; k0 < K; k0 += 8) {
        const bool more = (k0 + 8) < K;
        if (more) {  // prefetch next step into registers (overlaps with FMAs)
            a4 = *(const float4*)(Aptr + k0 + 8);
            b4 = *(const float4*)(Bptr + (size_t)(k0 + 8) * N);
        }
        #pragma unroll
        for (int k = 0; k < 8; k++) {
            float a[8], bf[8];
            ((float4*)a)[0]  = *(const float4*)&As[buf][k][ty * 8];
            ((float4*)a)[1]  = *(const float4*)&As[buf][k][ty * 8 + 4];
            ((float4*)bf)[0] = *(const float4*)&Bs[buf][k][tx * 8];
            ((float4*)bf)[1] = *(const float4*)&Bs[buf][k][tx * 8 + 4];
            #pragma unroll
            for (int r = 0; r < 8; r++)
                #pragma unroll
                for (int c = 0; c < 8; c++) acc[r][c] += a[r] * bf[c];
        }
        if (more) {
            int nb = buf ^ 1;
            As[nb][ak + 0][am] = a4.x; As[nb][ak + 1][am] = a4.y;
            As[nb][ak + 2][am] = a4.z; As[nb][ak + 3][am] = a4.w;
            *(float4*)&Bs[nb][bk][bn] = b4;
            __syncthreads();
            buf = nb;
        }
    }

    #pragma unroll
    for (int r = 0; r < 8; r++) {
        int row = row0 + ty * 8 + r;
        #pragma unroll
        for (int cc = 0; cc < 8; cc += 4) {
            int col = col0 + tx * 8 + cc;
            float4 v = make_float4(acc[r][cc], acc[r][cc + 1],
                                   acc[r][cc + 2], acc[r][cc + 3]);
            if (bias) {
                float4 bb4 = *(const float4*)&bias[col];
                v.x += bb4.x; v.y += bb4.y; v.z += bb4.z; v.w += bb4.w;
            }
            if (OP == 1) {
                float4 r4 = *(const float4*)&R[(size_t)row * N + col];
                v.x += r4.x; v.y += r4.y; v.z += r4.z; v.w += r4.w;
            }
            if (OP == 2) {
                v.x = gelu_f(v.x); v.y = gelu_f(v.y);
                v.z = gelu_f(v.z); v.w = gelu_f(v.w);
            }
            *(float4*)&C[(size_t)row * N + col] = v;
        }
    }
}

// ---------------- fused window attention ----------------
// grid: (64 windows, 4 heads, 32 batch); 128 threads.
// qkv layout per token: [q(512) | k(512) | v(512)], channel = head*128 + d.
// shift folds the roll into gather AND scatter: u = (p + shift) % 56.
__global__ void attn_kernel(const float* __restrict__ qkv,
                            const float* __restrict__ pos,
                            float* __restrict__ out, int shift)
{
    __shared__ float KV[49 * 128];   // K transposed [d][j], then reused as V [j][d]
    __shared__ float S[49 * 49];     // softmax probs
    __shared__ float Qs[4][128];     // one q row per warp
    __shared__ float poss[169];      // 13x13 relative-pos table

    int tid = threadIdx.x;
    int win = blockIdx.x, head = blockIdx.y, bb = blockIdx.z;
    int win_i = win >> 3, win_j = win & 7;

    for (int idx = tid; idx < 169; idx += 128) poss[idx] = pos[idx];

    int d = tid;
    // load K transposed: KV[d*49 + j]
    for (int j = 0; j < 49; j++) {
        int wi = j / 7, wj = j % 7;
        int ui = (win_i * 7 + wi + shift) % 56;
        int uj = (win_j * 7 + wj + shift) % 56;
        KV[d * 49 + j] =
            qkv[(size_t)(bb * 3136 + ui * 56 + uj) * 1536 + 512 + head * 128 + d];
    }
    __syncthreads();

    int w = tid >> 5, l = tid & 31;
    int j1 = (l < 17) ? (l + 32) : 0;     // clamped second column index

    for (int i = w; i < 49; i += 4) {
        int wi = i / 7, wj = i % 7;
        int ui = (win_i * 7 + wi + shift) % 56;
        int uj = (win_j * 7 + wj + shift) % 56;
        const float* qp = &qkv[(size_t)(bb * 3136 + ui * 56 + uj) * 1536 + head * 128];
        __syncwarp();
        Qs[w][l] = qp[l]; Qs[w][l + 32] = qp[l + 32];
        Qs[w][l + 64] = qp[l + 64]; Qs[w][l + 96] = qp[l + 96];
        __syncwarp();

        float s0 = 0.f, s1 = 0.f;
        #pragma unroll 8
        for (int dd = 0; dd < 128; dd++) {
            float qv = Qs[w][dd];
            s0 += qv * KV[dd * 49 + l];
            s1 += qv * KV[dd * 49 + j1];
        }
        const float scale = 0.08838834764831845f;  // 128^-0.5
        int jj0 = l, jj1 = l + 32;
        float v0 = s0 * scale + poss[(jj0 / 7 - wi + 6) * 13 + (jj0 % 7 - wj + 6)];
        float v1 = (l < 17)
            ? s1 * scale + poss[(jj1 / 7 - wi + 6) * 13 + (jj1 % 7 - wj + 6)]
            : -3.0e38f;
        if (shift) {
            if (win_i == 7) {
                if ((i >= 28) != (jj0 >= 28)) v0 += NEGM;
                if (l < 17 && ((i >= 28) != (jj1 >= 28))) v1 += NEGM;
            }
            if (win_j == 7) {
                if ((wj >= 4) != (jj0 % 7 >= 4)) v0 += NEGM;
                if (l < 17 && ((wj >= 4) != (jj1 % 7 >= 4))) v1 += NEGM;
            }
        }
        // warp softmax over 49 entries (lane l holds j=l and j=l+32)
        float m = v0; if (l < 17) m = fmaxf(m, v1);
        #pragma unroll
        for (int o = 16; o; o >>= 1) m = fmaxf(m, __shfl_xor_sync(~0u, m, o));
        float e0 = expf(v0 - m);
        float e1 = (l < 17) ? expf(v1 - m) : 0.f;
        float sm = e0 + e1;
        #pragma unroll
        for (int o = 16; o; o >>= 1) sm += __shfl_xor_sync(~0u, sm, o);
        float inv = 1.f / sm;
        S[i * 49 + jj0] = e0 * inv;
        if (l < 17) S[i * 49 + jj1] = e1 * inv;
    }
    __syncthreads();

    // load V natural layout: KV[j*128 + d]
    for (int j = 0; j < 49; j++) {
        int wi = j / 7, wj = j % 7;
        int ui = (win_i * 7 + wi + shift) % 56;
        int uj = (win_j * 7 + wj + shift) % 56;
        KV[j * 128 + d] =
            qkv[(size_t)(bb * 3136 + ui * 56 + uj) * 1536 + 1024 + head * 128 + d];
    }
    __syncthreads();

    // out[i][d] = sum_j P[i][j] * V[j][d]; scatter with roll-back index
    for (int i = 0; i < 49; i++) {
        float acc = 0.f;
        #pragma unroll 7
        for (int j = 0; j < 49; j++) acc += S[i * 49 + j] * KV[j * 128 + d];
        int wi = i / 7, wj = i % 7;
        int ui = (win_i * 7 + wi + shift) % 56;
        int uj = (win_j * 7 + wj + shift) % 56;
        out[(size_t)(bb * 3136 + ui * 56 + uj) * 512 + head * 128 + d] = acc;
    }
}

// ---------------- host launcher ----------------
extern "C" void kernel_launch(void* const* d_in, const int* in_sizes, int n_in,
                              void* d_out, int out_size)
{
    const float* x    = (const float*)d_in[0];
    const float* w_pe = (const float*)d_in[1];
    const float* b_pe = (const float*)d_in[2];

    float *h, *xn, *qkv, *mid;
    cudaGetSymbolAddress((void**)&h,   g_h);
    cudaGetSymbolAddress((void**)&xn,  g_xn);
    cudaGetSymbolAddress((void**)&qkv, g_qkv);
    cudaGetSymbolAddress((void**)&mid, g_mid);
    float* out = (float*)d_out;

    patch_embed_kernel<<<T_TOK, 128>>>(x, w_pe, b_pe, h);

    for (int blk = 0; blk < 2; blk++) {
        const float* const* p = (const float* const*)(d_in + 3 + blk * 12);
        const float *ga1 = p[0], *be1 = p[1], *wqkv = p[2], *pos = p[3],
                    *wo  = p[4], *bo  = p[5], *ga2  = p[6], *be2 = p[7],
                    *w1  = p[8], *b1  = p[9], *w2   = p[10], *b2 = p[11];
        int shift = blk ? DISP : 0;
        float* fin = (blk == 1) ? out : h;

        ln_kernel<<<T_TOK, 128>>>(h, ga1, be1, xn);
        sgemm_kernel<0, DIM, QKV3><<<dim3(QKV3 / 128, T_TOK / 128), 256>>>(
            xn, wqkv, nullptr, nullptr, qkv);
        attn_kernel<<<dim3(64, HEADS, 32), 128>>>(qkv, pos, mid, shift);
        sgemm_kernel<1, INNER, DIM><<<dim3(1, T_TOK / 128), 256>>>(
            mid, wo, bo, h, h);
        ln_kernel<<<T_TOK, 128>>>(h, ga2, be2, xn);
        sgemm_kernel<2, DIM, MLPD><<<dim3(MLPD / 128, T_TOK / 128), 256>>>(
            xn, w1, b1, nullptr, mid);
        sgemm_kernel<1, MLPD, DIM><<<dim3(1, T_TOK / 128), 256>>>(
            mid, w2, b2, h, fin);
    }
}

// round 5
// speedup vs baseline: 2.5254x; 2.5254x over previous
#include <cuda_runtime.h>
#include <math.h>
#include <stdint.h>

#define T_TOK 100352   // 32*56*56 tokens
#define DIM   128
#define INNER 512
#define QKV3  1536
#define MLPD  512
#define HEADS 4
#define DISP  3
#define NEGM  (-1e9f)

// ---------------- scratch (static device globals; no allocations) ----------------
__device__ float g_h  [T_TOK * DIM];
__device__ float g_xn [T_TOK * DIM];
__device__ float g_qkv[T_TOK * QKV3];
__device__ float g_mid[T_TOK * INNER];

// ---------------- patch embed ----------------
__global__ void patch_embed_kernel(const float* __restrict__ x,
                                   const float* __restrict__ w,
                                   const float* __restrict__ b,
                                   float* __restrict__ out)
{
    int t = blockIdx.x, n = threadIdx.x;
    __shared__ float s[48];
    int bb = t / 3136, rem = t % 3136, ph = rem / 56, pw = rem % 56;
    if (n < 48) {
        int c = n >> 4, pi = (n >> 2) & 3, pj = n & 3;
        s[n] = x[((size_t)(bb * 3 + c) * 224 + (ph * 4 + pi)) * 224 + (pw * 4 + pj)];
    }
    __syncthreads();
    float acc = b[n];
    #pragma unroll
    for (int f = 0; f < 48; f++) acc += s[f] * w[f * DIM + n];
    out[(size_t)t * DIM + n] = acc;
}

// ---------------- LayerNorm ----------------
__global__ void ln_kernel(const float* __restrict__ x,
                          const float* __restrict__ g,
                          const float* __restrict__ b,
                          float* __restrict__ y)
{
    int t = blockIdx.x, c = threadIdx.x;
    float v = x[(size_t)t * DIM + c];
    __shared__ float red[4];
    float s = v;
    #pragma unroll
    for (int o = 16; o; o >>= 1) s += __shfl_xor_sync(~0u, s, o);
    if ((c & 31) == 0) red[c >> 5] = s;
    __syncthreads();
    float mean = (red[0] + red[1] + red[2] + red[3]) * (1.f / 128.f);
    __syncthreads();
    float d = v - mean;
    s = d * d;
    #pragma unroll
    for (int o = 16; o; o >>= 1) s += __shfl_xor_sync(~0u, s, o);
    if ((c & 31) == 0) red[c >> 5] = s;
    __syncthreads();
    float var = (red[0] + red[1] + red[2] + red[3]) * (1.f / 128.f);
    y[(size_t)t * DIM + c] = d * rsqrtf(var + 1e-5f) * g[c] + b[c];
}

// ---------------- TF32 tensor-core GEMM 128x128xBK16, 8 warps ----------------
__device__ __forceinline__ float gelu_f(float v)
{
    return 0.5f * v * (1.f + erff(v * 0.70710678118654752f));
}

__device__ __forceinline__ float tf32r(float x)
{
    uint32_t u;
    asm("cvt.rna.tf32.f32 %0, %1;" : "=r"(u) : "f"(x));
    return __uint_as_float(u);
}

__device__ __forceinline__ void mma_tf32(float c[4], const uint32_t a[4], const uint32_t b[2])
{
    asm volatile(
        "mma.sync.aligned.m16n8k8.row.col.f32.tf32.tf32.f32 "
        "{%0,%1,%2,%3}, {%4,%5,%6,%7}, {%8,%9}, {%0,%1,%2,%3};"
        : "+f"(c[0]), "+f"(c[1]), "+f"(c[2]), "+f"(c[3])
        : "r"(a[0]), "r"(a[1]), "r"(a[2]), "r"(a[3]), "r"(b[0]), "r"(b[1]));
}

// OP: 0 = +bias(optional), 1 = +bias +residual R, 2 = +bias then exact GELU
template <int OP, int K, int N>
__global__ void __launch_bounds__(256)
tgemm_kernel(const float* __restrict__ A, const float* __restrict__ B,
             const float* __restrict__ bias, const float* __restrict__ R,
             float* __restrict__ C)
{
    __shared__ float As[2][16][136];   // [k][m], pad 136 -> conflict-free frags
    __shared__ float Bs[2][16][136];   // [k][n]

    int tid  = threadIdx.x;
    int lane = tid & 31, wid = tid >> 5;
    int g = lane >> 2, tig = lane & 3;
    int warp_m = (wid & 1) * 64, warp_n = (wid >> 1) * 32;
    int row0 = blockIdx.y * 128, col0 = blockIdx.x * 128;

    int am = tid & 127, ak = (tid >> 7) * 8;   // A loader
    int bn = (tid & 31) * 4, bk = tid >> 5;    // B loader (bk 0..7)

    float acc[4][4][4];
    #pragma unroll
    for (int mt = 0; mt < 4; mt++)
        #pragma unroll
        for (int nt = 0; nt < 4; nt++)
            #pragma unroll
            for (int r = 0; r < 4; r++) acc[mt][nt][r] = 0.f;

    const float* Aptr = A + (size_t)(row0 + am) * K + ak;
    const float* Bptr = B + (size_t)bk * N + col0 + bn;

    float4 a0 = *(const float4*)(Aptr);
    float4 a1 = *(const float4*)(Aptr + 4);
    float4 b0 = *(const float4*)(Bptr);
    float4 b1 = *(const float4*)(Bptr + (size_t)8 * N);

    As[0][ak + 0][am] = tf32r(a0.x); As[0][ak + 1][am] = tf32r(a0.y);
    As[0][ak + 2][am] = tf32r(a0.z); As[0][ak + 3][am] = tf32r(a0.w);
    As[0][ak + 4][am] = tf32r(a1.x); As[0][ak + 5][am] = tf32r(a1.y);
    As[0][ak + 6][am] = tf32r(a1.z); As[0][ak + 7][am] = tf32r(a1.w);
    {
        float4 c0 = make_float4(tf32r(b0.x), tf32r(b0.y), tf32r(b0.z), tf32r(b0.w));
        float4 c1 = make_float4(tf32r(b1.x), tf32r(b1.y), tf32r(b1.z), tf32r(b1.w));
        *(float4*)&Bs[0][bk][bn] = c0;
        *(float4*)&Bs[0][bk + 8][bn] = c1;
    }
    __syncthreads();

    int buf = 0;
    #pragma unroll 2
    for (int k0 = 0; k0 < K; k0 += 16) {
        const bool more = (k0 + 16) < K;
        if (more) {
            a0 = *(const float4*)(Aptr + k0 + 16);
            a1 = *(const float4*)(Aptr + k0 + 20);
            b0 = *(const float4*)(Bptr + (size_t)(k0 + 16) * N);
            b1 = *(const float4*)(Bptr + (size_t)(k0 + 24) * N);
        }
        #pragma unroll
        for (int ks = 0; ks < 2; ks++) {
            int kb = ks * 8;
            uint32_t af[4][4], bfr[4][2];
            #pragma unroll
            for (int mt = 0; mt < 4; mt++) {
                int m0 = warp_m + mt * 16;
                af[mt][0] = __float_as_uint(As[buf][kb + tig    ][m0 + g    ]);
                af[mt][1] = __float_as_uint(As[buf][kb + tig    ][m0 + g + 8]);
                af[mt][2] = __float_as_uint(As[buf][kb + tig + 4][m0 + g    ]);
                af[mt][3] = __float_as_uint(As[buf][kb + tig + 4][m0 + g + 8]);
            }
            #pragma unroll
            for (int nt = 0; nt < 4; nt++) {
                int n0 = warp_n + nt * 8;
                bfr[nt][0] = __float_as_uint(Bs[buf][kb + tig    ][n0 + g]);
                bfr[nt][1] = __float_as_uint(Bs[buf][kb + tig + 4][n0 + g]);
            }
            #pragma unroll
            for (int mt = 0; mt < 4; mt++)
                #pragma unroll
                for (int nt = 0; nt < 4; nt++)
                    mma_tf32(acc[mt][nt], af[mt], bfr[nt]);
        }
        if (more) {
            int nb = buf ^ 1;
            As[nb][ak + 0][am] = tf32r(a0.x); As[nb][ak + 1][am] = tf32r(a0.y);
            As[nb][ak + 2][am] = tf32r(a0.z); As[nb][ak + 3][am] = tf32r(a0.w);
            As[nb][ak + 4][am] = tf32r(a1.x); As[nb][ak + 5][am] = tf32r(a1.y);
            As[nb][ak + 6][am] = tf32r(a1.z); As[nb][ak + 7][am] = tf32r(a1.w);
            float4 c0 = make_float4(tf32r(b0.x), tf32r(b0.y), tf32r(b0.z), tf32r(b0.w));
            float4 c1 = make_float4(tf32r(b1.x), tf32r(b1.y), tf32r(b1.z), tf32r(b1.w));
            *(float4*)&Bs[nb][bk][bn] = c0;
            *(float4*)&Bs[nb][bk + 8][bn] = c1;
            __syncthreads();
            buf = nb;
        }
    }

    // epilogue: c0(r,c) c1(r,c+1) c2(r+8,c) c3(r+8,c+1); r=..+g, c=..+2*tig
    #pragma unroll
    for (int mt = 0; mt < 4; mt++) {
        #pragma unroll
        for (int nt = 0; nt < 4; nt++) {
            int r = row0 + warp_m + mt * 16 + g;
            int c = col0 + warp_n + nt * 8 + 2 * tig;
            float v00 = acc[mt][nt][0], v01 = acc[mt][nt][1];
            float v10 = acc[mt][nt][2], v11 = acc[mt][nt][3];
            if (bias) {
                float2 bb = *(const float2*)&bias[c];
                v00 += bb.x; v01 += bb.y; v10 += bb.x; v11 += bb.y;
            }
            if (OP == 1) {
                float2 r0 = *(const float2*)&R[(size_t)r * N + c];
                float2 r1 = *(const float2*)&R[(size_t)(r + 8) * N + c];
                v00 += r0.x; v01 += r0.y; v10 += r1.x; v11 += r1.y;
            }
            if (OP == 2) {
                v00 = gelu_f(v00); v01 = gelu_f(v01);
                v10 = gelu_f(v10); v11 = gelu_f(v11);
            }
            float2 o0 = make_float2(v00, v01), o1 = make_float2(v10, v11);
            *(float2*)&C[(size_t)r * N + c] = o0;
            *(float2*)&C[(size_t)(r + 8) * N + c] = o1;
        }
    }
}

// ---------------- fused window attention (V in registers) ----------------
// grid: (64 windows, 4 heads, 32 batch); 128 threads.
__global__ void attn_kernel(const float* __restrict__ qkv,
                            const float* __restrict__ pos,
                            float* __restrict__ out, int shift)
{
    __shared__ float KT[49 * 128];   // K transposed [d][j]
    __shared__ float S[49 * 52];     // softmax probs, padded rows
    __shared__ float Qs[4][128];
    __shared__ float poss[169];

    int tid = threadIdx.x;
    int win = blockIdx.x, head = blockIdx.y, bb = blockIdx.z;
    int win_i = win >> 3, win_j = win & 7;

    for (int idx = tid; idx < 169; idx += 128) poss[idx] = pos[idx];

    int d = tid;
    // K transposed into smem; V into registers (gmem latency overlaps QK below)
    float vreg[49];
    #pragma unroll
    for (int j = 0; j < 49; j++) {
        int wi = j / 7, wj = j % 7;
        int ui = (win_i * 7 + wi + shift) % 56;
        int uj = (win_j * 7 + wj + shift) % 56;
        size_t base = (size_t)(bb * 3136 + ui * 56 + uj) * 1536 + head * 128 + d;
        KT[d * 49 + j] = qkv[base + 512];
        vreg[j]        = qkv[base + 1024];
    }
    __syncthreads();

    int w = tid >> 5, l = tid & 31;
    int j1 = (l < 17) ? (l + 32) : 0;

    for (int i = w; i < 49; i += 4) {
        int wi = i / 7, wj = i % 7;
        int ui = (win_i * 7 + wi + shift) % 56;
        int uj = (win_j * 7 + wj + shift) % 56;
        const float* qp = &qkv[(size_t)(bb * 3136 + ui * 56 + uj) * 1536 + head * 128];
        __syncwarp();
        Qs[w][l] = qp[l]; Qs[w][l + 32] = qp[l + 32];
        Qs[w][l + 64] = qp[l + 64]; Qs[w][l + 96] = qp[l + 96];
        __syncwarp();

        float s0 = 0.f, s1 = 0.f;
        #pragma unroll 8
        for (int dd = 0; dd < 128; dd++) {
            float qv = Qs[w][dd];
            s0 += qv * KT[dd * 49 + l];
            s1 += qv * KT[dd * 49 + j1];
        }
        const float scale = 0.08838834764831845f;
        int jj0 = l, jj1 = l + 32;
        float v0 = s0 * scale + poss[(jj0 / 7 - wi + 6) * 13 + (jj0 % 7 - wj + 6)];
        float v1 = (l < 17)
            ? s1 * scale + poss[(jj1 / 7 - wi + 6) * 13 + (jj1 % 7 - wj + 6)]
            : -3.0e38f;
        if (shift) {
            if (win_i == 7) {
                if ((i >= 28) != (jj0 >= 28)) v0 += NEGM;
                if (l < 17 && ((i >= 28) != (jj1 >= 28))) v1 += NEGM;
            }
            if (win_j == 7) {
                if ((wj >= 4) != (jj0 % 7 >= 4)) v0 += NEGM;
                if (l < 17 && ((wj >= 4) != (jj1 % 7 >= 4))) v1 += NEGM;
            }
        }
        float m = v0; if (l < 17) m = fmaxf(m, v1);
        #pragma unroll
        for (int o = 16; o; o >>= 1) m = fmaxf(m, __shfl_xor_sync(~0u, m, o));
        float e0 = expf(v0 - m);
        float e1 = (l < 17) ? expf(v1 - m) : 0.f;
        float sm = e0 + e1;
        #pragma unroll
        for (int o = 16; o; o >>= 1) sm += __shfl_xor_sync(~0u, sm, o);
        float inv = 1.f / sm;
        S[i * 52 + jj0] = e0 * inv;
        if (l < 17) S[i * 52 + jj1] = e1 * inv;
    }
    __syncthreads();

    // AV: out[i][d] = sum_j S[i][j] * vreg[j]; S read as warp-broadcast float4
    #pragma unroll 1
    for (int i = 0; i < 49; i++) {
        const float* srow = &S[i * 52];
        float acc = 0.f;
        #pragma unroll
        for (int jq = 0; jq < 12; jq++) {
            float4 s4 = *(const float4*)(srow + jq * 4);
            acc += s4.x * vreg[jq * 4 + 0] + s4.y * vreg[jq * 4 + 1]
                 + s4.z * vreg[jq * 4 + 2] + s4.w * vreg[jq * 4 + 3];
        }
        acc += srow[48] * vreg[48];
        int wi = i / 7, wj = i % 7;
        int ui = (win_i * 7 + wi + shift) % 56;
        int uj = (win_j * 7 + wj + shift) % 56;
        out[(size_t)(bb * 3136 + ui * 56 + uj) * 512 + head * 128 + d] = acc;
    }
}

// ---------------- host launcher ----------------
extern "C" void kernel_launch(void* const* d_in, const int* in_sizes, int n_in,
                              void* d_out, int out_size)
{
    const float* x    = (const float*)d_in[0];
    const float* w_pe = (const float*)d_in[1];
    const float* b_pe = (const float*)d_in[2];

    float *h, *xn, *qkv, *mid;
    cudaGetSymbolAddress((void**)&h,   g_h);
    cudaGetSymbolAddress((void**)&xn,  g_xn);
    cudaGetSymbolAddress((void**)&qkv, g_qkv);
    cudaGetSymbolAddress((void**)&mid, g_mid);
    float* out = (float*)d_out;

    patch_embed_kernel<<<T_TOK, 128>>>(x, w_pe, b_pe, h);

    for (int blk = 0; blk < 2; blk++) {
        const float* const* p = (const float* const*)(d_in + 3 + blk * 12);
        const float *ga1 = p[0], *be1 = p[1], *wqkv = p[2], *pos = p[3],
                    *wo  = p[4], *bo  = p[5], *ga2  = p[6], *be2 = p[7],
                    *w1  = p[8], *b1  = p[9], *w2   = p[10], *b2 = p[11];
        int shift = blk ? DISP : 0;
        float* fin = (blk == 1) ? out : h;

        ln_kernel<<<T_TOK, 128>>>(h, ga1, be1, xn);
        tgemm_kernel<0, DIM, QKV3><<<dim3(QKV3 / 128, T_TOK / 128), 256>>>(
            xn, wqkv, nullptr, nullptr, qkv);
        attn_kernel<<<dim3(64, HEADS, 32), 128>>>(qkv, pos, mid, shift);
        tgemm_kernel<1, INNER, DIM><<<dim3(1, T_TOK / 128), 256>>>(
            mid, wo, bo, h, h);
        ln_kernel<<<T_TOK, 128>>>(h, ga2, be2, xn);
        tgemm_kernel<2, DIM, MLPD><<<dim3(MLPD / 128, T_TOK / 128), 256>>>(
            xn, w1, b1, nullptr, mid);
        tgemm_kernel<1, MLPD, DIM><<<dim3(1, T_TOK / 128), 256>>>(
            mid, w2, b2, h, fin);
    }
}